// round 7
// baseline (speedup 1.0000x reference)
#include <cuda_runtime.h>

// Problem constants (fixed by setup_inputs)
#define B_ 16
#define T_ 8192
#define D_ 64
#define D2 (D_ / 2)       // 32 float2 columns
#define CHUNK 16          // == WINDOW
#define CPT 4             // chunks per thread -> 64 timesteps per thread
#define TPT (CHUNK * CPT) // 64
#define YDIM 2
#define BLOCK_T (TPT * YDIM) // 128 timesteps per block

__device__ __forceinline__ float fexp2(float x) {
    float y; asm("ex2.approx.ftz.f32 %0, %1;" : "=f"(y) : "f"(x)); return y;
}
__device__ __forceinline__ float flog2(float x) {
    float y; asm("lg2.approx.ftz.f32 %0, %1;" : "=f"(y) : "f"(x)); return y;
}

// out[b,t,d] = -(1/5) * log( sum_{k=0..15} exp(-5 * x[b, max(t-k,0), d]) )
// Chunked prefix/suffix decomposition, float2 over D, streaming stores.
// R6 post-mortem: MUFU pipe ~80% utilized (ex2+lg2) and each warp's MUFU
// burst delayed the next chunk's loads -> DRAM stuck at ~57%. Fix: explicit
// one-chunk-ahead load prefetch (vn) with a 128-reg budget so ptxas keeps
// the prefetch hoisted, and 64-thread blocks (grid 2048) for ~1% wave tail.
__global__ __launch_bounds__(64, 8) void always_kernel(
    const float* __restrict__ lower,
    const float* __restrict__ upper,
    float* __restrict__ out)
{
    const float C1 = -7.2134752044448169f;   // -5 * log2(e)
    const float C2 = -0.13862943611198906f;  // -ln(2) / 5

    const int d2 = threadIdx.x;              // 0..31 float2 column (coalesced)
    const int b  = blockIdx.y;               // 0..15
    const int tr = blockIdx.z;               // 0: lower, 1: upper
    const int t0 = blockIdx.x * BLOCK_T + threadIdx.y * TPT;

    const float* src = tr ? upper : lower;
    float*       dst = out + (size_t)tr * ((size_t)B_ * T_ * D_);

    const float2* col  = (const float2*)src + (size_t)b * T_ * D2 + d2;
    float2*       ocol = (float2*)dst      + (size_t)b * T_ * D2 + d2;

    // Issue chunk-0 loads FIRST (longest dependency distance), then halo.
    float2 vc[16], vh[16];
    #pragma unroll
    for (int r = 0; r < 16; r++) vc[r] = col[(t0 + r) * D2];
    #pragma unroll
    for (int k = 1; k < 16; k++) {
        int t = t0 - 16 + k;
        if (t < 0) t = 0;                    // clamp reproduces h0 replication
        vh[k] = col[t * D2];
    }

    // Halo suffix sums: sfx/sfy[k] = sum_{j>=k} exp(-5*x[t0-16+j]).
    float sfx[16], sfy[16];
    #pragma unroll
    for (int k = 1; k < 16; k++) {
        sfx[k] = fexp2(vh[k].x * C1);
        sfy[k] = fexp2(vh[k].y * C1);
    }
    #pragma unroll
    for (int k = 14; k >= 1; k--) { sfx[k] += sfx[k + 1]; sfy[k] += sfy[k + 1]; }

    #pragma unroll
    for (int c = 0; c < CPT; c++) {
        const int tc = t0 + c * CHUNK;

        // Prefetch next chunk's 16 LDG.64 BEFORE this chunk's MUFU burst.
        float2 vn[16];
        if (c + 1 < CPT) {
            #pragma unroll
            for (int r = 0; r < 16; r++) vn[r] = col[(tc + CHUNK + r) * D2];
        }

        // MUFU burst for the current chunk (loads already arrived).
        float ex[16], ey[16];
        #pragma unroll
        for (int r = 0; r < 16; r++) {
            ex[r] = fexp2(vc[r].x * C1);
            ey[r] = fexp2(vc[r].y * C1);
        }

        // window_sum = prefix_cur[r] + suffix_prev[r+1] (exact 16-term sum).
        float px = 0.0f, py = 0.0f;
        #pragma unroll
        for (int r = 0; r < 16; r++) {
            px += ex[r];
            py += ey[r];
            float wx = (r < 15) ? (px + sfx[r + 1]) : px;
            float wy = (r < 15) ? (py + sfy[r + 1]) : py;
            float2 o;
            o.x = flog2(wx) * C2;
            o.y = flog2(wy) * C2;
            __stcs(&ocol[(tc + r) * D2], o);   // evict-first: outputs never re-read
        }

        // This chunk's suffix sums become "previous" for the next chunk.
        if (c + 1 < CPT) {
            float rx = 0.0f, ry = 0.0f;
            #pragma unroll
            for (int k = 15; k >= 1; k--) {
                rx += ex[k]; sfx[k] = rx;
                ry += ey[k]; sfy[k] = ry;
            }
            // Full unroll: this is a register rename, not a copy loop.
            #pragma unroll
            for (int r = 0; r < 16; r++) vc[r] = vn[r];
        }
    }
}

extern "C" void kernel_launch(void* const* d_in, const int* in_sizes, int n_in,
                              void* d_out, int out_size) {
    const float* lower = (const float*)d_in[0];
    const float* upper = (const float*)d_in[1];
    float* out = (float*)d_out;

    dim3 block(D2, YDIM);                  // 32 x 2 = 64 threads
    dim3 grid(T_ / BLOCK_T, B_, 2);        // 64 x 16 x 2 = 2048 blocks
    always_kernel<<<grid, block>>>(lower, upper, out);
}

// round 8
// speedup vs baseline: 1.0992x; 1.0992x over previous
#include <cuda_runtime.h>

// Problem constants (fixed by setup_inputs)
#define B_ 16
#define T_ 8192
#define D_ 64
#define D2 (D_ / 2)       // 32 float2 columns
#define CHUNK 16          // == WINDOW
#define CPT 4             // chunks per thread -> 64 timesteps per thread
#define TPT (CHUNK * CPT) // 64
#define YDIM 2
#define BLOCK_T (TPT * YDIM) // 128 timesteps per block

__device__ __forceinline__ float fexp2(float x) {
    float y; asm("ex2.approx.ftz.f32 %0, %1;" : "=f"(y) : "f"(x)); return y;
}
__device__ __forceinline__ float flog2(float x) {
    float y; asm("lg2.approx.ftz.f32 %0, %1;" : "=f"(y) : "f"(x)); return y;
}

// out[b,t,d] = -(1/5) * log( sum_{k=0..15} exp(-5 * x[b, max(t-k,0), d]) )
// Chunked prefix/suffix decomposition, float2 over D, streaming stores.
// R8: in-place suffix construction (e[r] overwrites suf[r] right after
// suf[r] dies) eliminates the separate e[16] arrays -> ~30 regs freed;
// spent on 64-thread blocks / grid 2048 for finer load balance.
__global__ __launch_bounds__(64, 12) void always_kernel(
    const float* __restrict__ lower,
    const float* __restrict__ upper,
    float* __restrict__ out)
{
    const float C1 = -7.2134752044448169f;   // -5 * log2(e)
    const float C2 = -0.13862943611198906f;  // -ln(2) / 5

    const int d2 = threadIdx.x;              // 0..31 float2 column (coalesced)
    const int b  = blockIdx.y;               // 0..15
    const int tr = blockIdx.z;               // 0: lower, 1: upper
    const int t0 = blockIdx.x * BLOCK_T + threadIdx.y * TPT;

    const float* src = tr ? upper : lower;
    float*       dst = out + (size_t)tr * ((size_t)B_ * T_ * D_);

    const float2* col  = (const float2*)src + (size_t)b * T_ * D2 + d2;
    float2*       ocol = (float2*)dst      + (size_t)b * T_ * D2 + d2;

    // Halo suffix sums of the 15 preceding (index-clamped) timesteps.
    // Clamp to 0 reproduces h0's replication of x[:,0,:] exactly
    // (duplicates ARE counted in the logsumexp, matching the reference).
    float sfx[16], sfy[16];                  // slots 1..15 used
    {
        float2 vh[16];
        #pragma unroll
        for (int k = 1; k < 16; k++) {
            int t = t0 - 16 + k;
            if (t < 0) t = 0;
            vh[k] = col[t * D2];
        }
        #pragma unroll
        for (int k = 1; k < 16; k++) {
            sfx[k] = fexp2(vh[k].x * C1);
            sfy[k] = fexp2(vh[k].y * C1);
        }
        #pragma unroll
        for (int k = 14; k >= 1; k--) { sfx[k] += sfx[k + 1]; sfy[k] += sfy[k + 1]; }
    }

    #pragma unroll 1
    for (int c = 0; c < CPT; c++) {
        const int tc = t0 + c * CHUNK;

        // 16 independent LDG.64 -> high MLP, 256B per warp per slot.
        float2 v[16];
        #pragma unroll
        for (int r = 0; r < 16; r++) v[r] = col[(tc + r) * D2];

        // Fused pass: window_sum = prefix_cur[r] + suffix_prev[r+1].
        // e[r] is written into sf[r] IN PLACE: sf[r] was last read at step
        // r-1, so the slot is dead by the time step r overwrites it.
        float px = 0.0f, py = 0.0f;
        #pragma unroll
        for (int r = 0; r < 16; r++) {
            float ex = fexp2(v[r].x * C1);
            float ey = fexp2(v[r].y * C1);
            px += ex;
            py += ey;
            float wx = (r < 15) ? (px + sfx[r + 1]) : px;
            float wy = (r < 15) ? (py + sfy[r + 1]) : py;
            float2 o;
            o.x = flog2(wx) * C2;
            o.y = flog2(wy) * C2;
            __stcs(&ocol[(tc + r) * D2], o);   // evict-first: outputs never re-read
            if (r >= 1) { sfx[r] = ex; sfy[r] = ey; }  // e[0] never needed again
        }

        // Reverse-accumulate in place -> suffix sums for the next chunk.
        if (c + 1 < CPT) {
            #pragma unroll
            for (int k = 14; k >= 1; k--) { sfx[k] += sfx[k + 1]; sfy[k] += sfy[k + 1]; }
        }
    }
}

extern "C" void kernel_launch(void* const* d_in, const int* in_sizes, int n_in,
                              void* d_out, int out_size) {
    const float* lower = (const float*)d_in[0];
    const float* upper = (const float*)d_in[1];
    float* out = (float*)d_out;

    dim3 block(D2, YDIM);                  // 32 x 2 = 64 threads
    dim3 grid(T_ / BLOCK_T, B_, 2);        // 64 x 16 x 2 = 2048 blocks
    always_kernel<<<grid, block>>>(lower, upper, out);
}